// round 15
// baseline (speedup 1.0000x reference)
#include <cuda_runtime.h>
#include <cstdint>

#define N_V    12288
#define D_F    32
#define N_E    196608
#define BLK    512                 // row/col block size
#define NB     (N_V / BLK)         // 24 blocks
#define NPAIR  (NB * (NB - 1) / 2) // 276 off-diagonal tiles
#define NB6    (NB * 6)            // per-vertex contribution slots
#define CJ     16                  // j-chunk
#define NCH    (BLK / CJ)          // 32 chunks per tile
#define DSTRIDE 520                // dbuf row stride (words): conflict-free
#define SCALE  20.0f
#define INV_S2 (1.0f / (SCALE * SCALE))
#define EPSF   1e-12f
#define BIGI   0x7FFFFFFF

// off-kernel dynamic smem word layout
#define W_BQ    0                          // 4096 u32  (512 rows x 8)
#define W_BSQ   4096                       // 512 int
#define W_DBUF  4608                       // 16 x 520 = 8320 int
#define W_CBUF  (4608 + 8320)              // 16 x 8 x 6 = 768 int
#define OFF_WORDS (W_CBUF + 768)           // 13696
#define OFF_BYTES (OFF_WORDS * 4)          // 54784

__device__ uint32_t g_qx[N_V * 8];         // int8-packed rows
__device__ int      g_isq[N_V];            // integer squared norms
__device__ int      g_part[N_V * NB6];     // per-vertex per-block top-6
__device__ float    g_v[N_V];

__device__ __forceinline__ void ins6i(int (&m)[6], int d) {
    int c4 = max(m[4], d);
    int c3 = max(m[3], d);
    int c2 = max(m[2], d);
    int c1 = max(m[1], d);
    int c0 = max(m[0], d);
    m[5] = min(m[5], c4);
    m[4] = min(m[4], c3);
    m[3] = min(m[3], c2);
    m[2] = min(m[2], c1);
    m[0] = min(m[0], d);
    m[1] = min(m[1], c0);
}

// ---------------------------------------------------------------------------
// Kernel 1: quantize x -> int8 (scale 20), integer squared norms
// ---------------------------------------------------------------------------
__global__ void conv_kernel(const float* __restrict__ x) {
    int i = blockIdx.x * blockDim.x + threadIdx.x;
    if (i < N_V) {
        const float4* xr = reinterpret_cast<const float4*>(x + (size_t)i * D_F);
        uint32_t pk[8];
        int isq = 0;
        #pragma unroll
        for (int q = 0; q < 8; q++) {
            float4 v = xr[q];
            int q0 = __float2int_rn(fminf(fmaxf(v.x * SCALE, -127.f), 127.f));
            int q1 = __float2int_rn(fminf(fmaxf(v.y * SCALE, -127.f), 127.f));
            int q2 = __float2int_rn(fminf(fmaxf(v.z * SCALE, -127.f), 127.f));
            int q3 = __float2int_rn(fminf(fmaxf(v.w * SCALE, -127.f), 127.f));
            pk[q] = (uint32_t)(q0 & 0xFF) | ((uint32_t)(q1 & 0xFF) << 8) |
                    ((uint32_t)(q2 & 0xFF) << 16) | ((uint32_t)(q3 & 0xFF) << 24);
            isq = __dp4a((int)pk[q], (int)pk[q], isq);
        }
        g_isq[i] = isq;
        uint4* dst = reinterpret_cast<uint4*>(g_qx + (size_t)i * 8);
        dst[0] = make_uint4(pk[0], pk[1], pk[2], pk[3]);
        dst[1] = make_uint4(pk[4], pk[5], pk[6], pk[7]);
    }
}

// ---------------------------------------------------------------------------
// Kernel 2a: diagonal tiles — exact top-6 of each row within its own block
// (includes self d=0). Writes contribution slot a.
// Grid NB*4, 128 threads (each quarter handles 128 rows).
// ---------------------------------------------------------------------------
__global__ void __launch_bounds__(128) knn_diag_kernel() {
    __shared__ uint32_t tile[BLK * 8];   // 16 KB
    __shared__ int      sqt[BLK];

    const int t   = threadIdx.x;
    const int a   = blockIdx.x >> 2;
    const int row = a * BLK + (blockIdx.x & 3) * 128 + t;
    const int jb  = a * BLK;

    uint32_t rq[8];
    {
        const uint4* p = reinterpret_cast<const uint4*>(g_qx + (size_t)row * 8);
        uint4 u = p[0], v = p[1];
        rq[0] = u.x; rq[1] = u.y; rq[2] = u.z; rq[3] = u.w;
        rq[4] = v.x; rq[5] = v.y; rq[6] = v.z; rq[7] = v.w;
    }
    {
        const uint4* src = reinterpret_cast<const uint4*>(g_qx + (size_t)jb * 8);
        uint4* dst = reinterpret_cast<uint4*>(tile);
        #pragma unroll
        for (int q = 0; q < 8; q++) dst[t + q * 128] = src[t + q * 128];
        #pragma unroll
        for (int q = 0; q < 4; q++) sqt[t + q * 128] = g_isq[jb + t + q * 128];
    }
    __syncthreads();

    int m[6] = {BIGI, BIGI, BIGI, BIGI, BIGI, BIGI};
    #pragma unroll 2
    for (int j = 0; j < BLK; j++) {
        const uint4 va = *reinterpret_cast<const uint4*>(&tile[j * 8]);
        const uint4 vb = *reinterpret_cast<const uint4*>(&tile[j * 8 + 4]);
        int acc = __dp4a((int)va.x, (int)rq[0], 0);
        acc = __dp4a((int)va.y, (int)rq[1], acc);
        acc = __dp4a((int)va.z, (int)rq[2], acc);
        acc = __dp4a((int)va.w, (int)rq[3], acc);
        acc = __dp4a((int)vb.x, (int)rq[4], acc);
        acc = __dp4a((int)vb.y, (int)rq[5], acc);
        acc = __dp4a((int)vb.z, (int)rq[6], acc);
        acc = __dp4a((int)vb.w, (int)rq[7], acc);
        int ds = sqt[j] - acc - acc;     // shifted by -isq_row (monotone)
        if (ds < m[5]) ins6i(m, ds);
    }
    const int isq = g_isq[row];
    int* dst = g_part + (size_t)row * NB6 + a * 6;
    #pragma unroll
    for (int q = 0; q < 6; q++) dst[q] = m[q] + isq;
}

// ---------------------------------------------------------------------------
// Kernel 2b: off-diagonal tiles (a < b), each distance computed ONCE.
// Phase 1 (MAC): 128 thr x 4 a-rows, 32 dp4a / j-iter (R6 floor density);
//   row-side guarded register top-6; unconditional STS of d into dbuf.
// Phase 2: column-wise re-read of dbuf (conflict-free stride 520), guarded
//   register top-6 per (column, eighth), 3-round smem merge -> exact
//   per-tile column top-6 -> g_part slot a. No atomics anywhere.
// ---------------------------------------------------------------------------
__global__ void __launch_bounds__(128) knn_off_kernel() {
    extern __shared__ int smem[];
    uint32_t* bq   = reinterpret_cast<uint32_t*>(smem + W_BQ);
    int*      bsq  = smem + W_BSQ;
    int*      dbuf = smem + W_DBUF;
    int*      cbuf = smem + W_CBUF;

    // decode linear pair index -> (a, b), a < b
    int k = blockIdx.x, a = 0;
    while (k >= NB - 1 - a) { k -= NB - 1 - a; a++; }
    const int b = a + 1 + k;

    const int t  = threadIdx.x;
    const int jb = b * BLK;
    const int c  = t >> 3;          // phase-2 column within chunk (0..15)
    const int e  = t & 7;           // phase-2 eighth (0..7)

    // 4 a-row vectors in registers
    uint32_t rq[4][8];
    int      isqr[4];
    #pragma unroll
    for (int r = 0; r < 4; r++) {
        const int row = a * BLK + r * 128 + t;
        const uint4* p = reinterpret_cast<const uint4*>(g_qx + (size_t)row * 8);
        uint4 u = p[0], v = p[1];
        rq[r][0] = u.x; rq[r][1] = u.y; rq[r][2] = u.z; rq[r][3] = u.w;
        rq[r][4] = v.x; rq[r][5] = v.y; rq[r][6] = v.z; rq[r][7] = v.w;
        isqr[r] = g_isq[row];
    }
    {   // b tile + norms
        const uint4* src = reinterpret_cast<const uint4*>(g_qx + (size_t)jb * 8);
        uint4* dst = reinterpret_cast<uint4*>(bq);
        #pragma unroll
        for (int q = 0; q < 8; q++) dst[t + q * 128] = src[t + q * 128];
        #pragma unroll
        for (int q = 0; q < 4; q++) bsq[t + q * 128] = g_isq[jb + t + q * 128];
    }
    __syncthreads();

    int m[4][6];
    #pragma unroll
    for (int r = 0; r < 4; r++)
        #pragma unroll
        for (int q = 0; q < 6; q++) m[r][q] = BIGI;

    #pragma unroll 1
    for (int ch = 0; ch < NCH; ch++) {
        const int jc0 = ch * CJ;
        // ---- phase 1: MAC + row-side select + store d ----
        #pragma unroll 2
        for (int jj = 0; jj < CJ; jj++) {
            const int j = jc0 + jj;
            const uint4 va = *reinterpret_cast<const uint4*>(&bq[j * 8]);
            const uint4 vb = *reinterpret_cast<const uint4*>(&bq[j * 8 + 4]);
            const int sj = bsq[j];
            #pragma unroll
            for (int r = 0; r < 4; r++) {
                int acc = __dp4a((int)va.x, (int)rq[r][0], 0);
                acc = __dp4a((int)va.y, (int)rq[r][1], acc);
                acc = __dp4a((int)va.z, (int)rq[r][2], acc);
                acc = __dp4a((int)va.w, (int)rq[r][3], acc);
                acc = __dp4a((int)vb.x, (int)rq[r][4], acc);
                acc = __dp4a((int)vb.y, (int)rq[r][5], acc);
                acc = __dp4a((int)vb.z, (int)rq[r][6], acc);
                acc = __dp4a((int)vb.w, (int)rq[r][7], acc);
                const int d = sj + isqr[r] - acc - acc;    // full d~2
                if (d < m[r][5]) ins6i(m[r], d);           // absorbed branch
                dbuf[jj * DSTRIDE + r * 128 + t] = d;      // unconditional STS
            }
        }
        __syncthreads();
        // ---- phase 2: column-side partial top-6 ----
        int mc[6] = {BIGI, BIGI, BIGI, BIGI, BIGI, BIGI};
        const int* dcol = dbuf + c * DSTRIDE + e;
        #pragma unroll 4
        for (int k2 = 0; k2 < 64; k2++) {
            const int d = dcol[8 * k2];
            if (d < mc[5]) ins6i(mc, d);
        }
        {
            int* cb = cbuf + t * 6;
            #pragma unroll
            for (int q = 0; q < 6; q++) cb[q] = mc[q];
        }
        __syncthreads();
        if (e < 4) {
            int* cb = cbuf + t * 6;
            const int* pb = cbuf + (t + 4) * 6;
            #pragma unroll
            for (int q = 0; q < 6; q++) ins6i(mc, pb[q]);
            #pragma unroll
            for (int q = 0; q < 6; q++) cb[q] = mc[q];
        }
        __syncthreads();
        if (e < 2) {
            int* cb = cbuf + t * 6;
            const int* pb = cbuf + (t + 2) * 6;
            #pragma unroll
            for (int q = 0; q < 6; q++) ins6i(mc, pb[q]);
            #pragma unroll
            for (int q = 0; q < 6; q++) cb[q] = mc[q];
        }
        __syncthreads();
        if (e == 0) {
            const int* pb = cbuf + (t + 1) * 6;
            #pragma unroll
            for (int q = 0; q < 6; q++) ins6i(mc, pb[q]);
            int* dst = g_part + (size_t)(jb + jc0 + c) * NB6 + a * 6;
            #pragma unroll
            for (int q = 0; q < 6; q++) dst[q] = mc[q];
        }
        __syncthreads();   // protect dbuf/cbuf before next chunk
    }

    // row-side flush: contribution slot b
    #pragma unroll
    for (int r = 0; r < 4; r++) {
        const int row = a * BLK + r * 128 + t;
        int* dst = g_part + (size_t)row * NB6 + b * 6;
        #pragma unroll
        for (int q = 0; q < 6; q++) dst[q] = m[r][q];
    }
}

// ---------------------------------------------------------------------------
// Kernel 3: warp per row — merge 24 block-contributions (144 ints, exact),
// then 6-round min-extraction. v = 1 - sum_{k=1..5} exp(-sqrt(d2))/6.
// ---------------------------------------------------------------------------
__global__ void __launch_bounds__(256) finalize_vertex_kernel(float* __restrict__ out) {
    const int row  = (blockIdx.x * blockDim.x + threadIdx.x) >> 5;
    const int lane = threadIdx.x & 31;
    if (row >= N_V) return;

    int m[6] = {BIGI, BIGI, BIGI, BIGI, BIGI, BIGI};
    const int* sp = g_part + (size_t)row * NB6;
    #pragma unroll
    for (int k = lane; k < NB6; k += 32) ins6i(m, sp[k]);

    int p = 0;
    float sum = 0.f;
    #pragma unroll
    for (int r = 0; r < 6; r++) {
        int cand = (p < 6) ? m[p] : BIGI;
        int mn = cand;
        #pragma unroll
        for (int mask = 16; mask >= 1; mask >>= 1)
            mn = min(mn, __shfl_xor_sync(0xFFFFFFFFu, mn, mask));
        unsigned ball = __ballot_sync(0xFFFFFFFFu, cand == mn);
        if (lane == __ffs(ball) - 1) p++;            // one lane consumes
        if (r > 0 && lane == 0) {                    // r=0 is self (d=0)
            float d2 = (float)mn * INV_S2;
            sum += expf(-sqrtf(fmaxf(d2, EPSF)));
        }
    }
    if (lane == 0) {
        float v = 1.f - sum * (1.f / 6.f);
        g_v[row] = v;
        out[2 * row]     = v;
        out[2 * row + 1] = 0.f;
    }
}

// ---------------------------------------------------------------------------
// Kernel 4: edge filtration, 8 edges/warp, 4 independent gathers per lane.
// Reference's per-edge pair sort is a no-op (outputs symmetric in (u,w)).
// ---------------------------------------------------------------------------
__global__ void __launch_bounds__(256) edge_kernel(const float* __restrict__ x,
                                                   const int* __restrict__ ei,
                                                   float* __restrict__ out) {
    const int warp = (blockIdx.x * blockDim.x + threadIdx.x) >> 5;
    const int lane = threadIdx.x & 31;
    const int k    = lane >> 2;          // edge group 0..7
    const int sub  = lane & 3;           // 8-float chunk 0..3
    const int e    = warp * 8 + k;
    if (e < N_E) {
        const int u = ei[e];
        const int w = ei[N_E + e];
        const float4* xu = reinterpret_cast<const float4*>(x + (size_t)u * D_F + sub * 8);
        const float4* xw = reinterpret_cast<const float4*>(x + (size_t)w * D_F + sub * 8);
        float4 a0 = xu[0], a1 = xu[1];
        float4 b0 = xw[0], b1 = xw[1];
        float dx = a0.x - b0.x, dy = a0.y - b0.y;
        float dz = a0.z - b0.z, dw = a0.w - b0.w;
        float s = dx * dx + dy * dy + dz * dz + dw * dw;
        dx = a1.x - b1.x; dy = a1.y - b1.y;
        dz = a1.z - b1.z; dw = a1.w - b1.w;
        s += dx * dx + dy * dy + dz * dz + dw * dw;
        s += __shfl_xor_sync(0xFFFFFFFFu, s, 1);
        s += __shfl_xor_sync(0xFFFFFFFFu, s, 2);
        if (sub == 0) {
            float n  = sqrtf(fmaxf(s, EPSF));
            float ev = fmaxf(g_v[u], g_v[w]);
            *reinterpret_cast<float2*>(out + 2 * (N_V + e)) =
                make_float2(ev, 1.f - expf(-n));
        }
    }
}

// ---------------------------------------------------------------------------
extern "C" void kernel_launch(void* const* d_in, const int* in_sizes, int n_in,
                              void* d_out, int out_size) {
    (void)in_sizes; (void)n_in; (void)out_size;
    const float* x   = (const float*)d_in[0];
    const int*   ei  = (const int*)d_in[1];
    float*       out = (float*)d_out;

    cudaFuncSetAttribute(knn_off_kernel,
                         cudaFuncAttributeMaxDynamicSharedMemorySize, OFF_BYTES);

    conv_kernel<<<(N_V + 255) / 256, 256>>>(x);
    knn_diag_kernel<<<NB * 4, 128>>>();
    knn_off_kernel<<<NPAIR, 128, OFF_BYTES>>>();
    finalize_vertex_kernel<<<(N_V * 32 + 255) / 256, 256>>>(out);
    edge_kernel<<<(N_E / 8 + 7) / 8, 256>>>(x, ei, out);
}

// round 16
// speedup vs baseline: 1.6214x; 1.6214x over previous
#include <cuda_runtime.h>
#include <cstdint>

#define N_V    12288
#define D_F    32
#define N_E    196608
#define THR    256
#define RPT    4                  // rows per thread
#define RB     (THR * RPT)        // 1024 rows per block
#define NBR    (N_V / RB)         // 12
#define SPLIT  24
#define JSEG   (N_V / SPLIT)      // 512
#define SCALE  20.0f
#define INV_S2 (1.0f / (SCALE * SCALE))
#define EPSF   1e-12f
#define BIGI   0x7FFFFFFF

__device__ uint32_t g_qx[N_V * 8];    // int8-packed rows (8 x u32 per row)
__device__ int      g_isq[N_V];       // integer squared norms
__device__ float    g_v[N_V];
__device__ int      g_part[N_V * SPLIT * 6];

__device__ __forceinline__ void ins6i(int (&m)[6], int d) {
    int c4 = max(m[4], d);
    int c3 = max(m[3], d);
    int c2 = max(m[2], d);
    int c1 = max(m[1], d);
    int c0 = max(m[0], d);
    m[5] = min(m[5], c4);
    m[4] = min(m[4], c3);
    m[3] = min(m[3], c2);
    m[2] = min(m[2], c1);
    m[0] = min(m[0], d);
    m[1] = min(m[1], c0);
}

// ---------------------------------------------------------------------------
// Kernel 1: quantize x -> int8 (scale 20), integer squared norms via dp4a
// ---------------------------------------------------------------------------
__global__ void conv_kernel(const float* __restrict__ x) {
    int i = blockIdx.x * blockDim.x + threadIdx.x;
    if (i < N_V) {
        const float4* xr = reinterpret_cast<const float4*>(x + (size_t)i * D_F);
        uint32_t pk[8];
        int isq = 0;
        #pragma unroll
        for (int q = 0; q < 8; q++) {
            float4 v = xr[q];
            int q0 = __float2int_rn(fminf(fmaxf(v.x * SCALE, -127.f), 127.f));
            int q1 = __float2int_rn(fminf(fmaxf(v.y * SCALE, -127.f), 127.f));
            int q2 = __float2int_rn(fminf(fmaxf(v.z * SCALE, -127.f), 127.f));
            int q3 = __float2int_rn(fminf(fmaxf(v.w * SCALE, -127.f), 127.f));
            pk[q] = (uint32_t)(q0 & 0xFF) | ((uint32_t)(q1 & 0xFF) << 8) |
                    ((uint32_t)(q2 & 0xFF) << 16) | ((uint32_t)(q3 & 0xFF) << 24);
            isq = __dp4a((int)pk[q], (int)pk[q], isq);
        }
        g_isq[i] = isq;
        uint4* dst = reinterpret_cast<uint4*>(g_qx + (size_t)i * 8);
        dst[0] = make_uint4(pk[0], pk[1], pk[2], pk[3]);
        dst[1] = make_uint4(pk[4], pk[5], pk[6], pk[7]);
    }
}

// ---------------------------------------------------------------------------
// Kernel 2: int8 full-scan knn (measured AT the dp4a pipe floor in R6).
// d~2(i,j) tracked in (isq_j - 2*idot) space; isq_i folded at the end.
// 256 threads x 4 rows/thread -> 32 dp4a per j-iteration (128 SMSP-cyc of
// dp4a-pipe demand; all selection rides the idle issue slots).
// Whole 512-j split staged in smem once: one sync pair per CTA.
// Grid (12, 24) = 288 CTAs = one balanced wave at occupancy 2.
// ---------------------------------------------------------------------------
__global__ void __launch_bounds__(THR, 2) knn_kernel() {
    __shared__ uint32_t tile[JSEG * 8];   // 16 KB
    __shared__ int      sqt[JSEG];        // 2 KB

    const int t    = threadIdx.x;
    const int base = blockIdx.x * RB;
    const int jb   = blockIdx.y * JSEG;

    // this thread's 4 row vectors (8 packed u32 each)
    uint32_t rq[RPT][8];
    #pragma unroll
    for (int r = 0; r < RPT; r++) {
        const uint4* p =
            reinterpret_cast<const uint4*>(g_qx + (size_t)(base + r * THR + t) * 8);
        uint4 a = p[0], b = p[1];
        rq[r][0] = a.x; rq[r][1] = a.y; rq[r][2] = a.z; rq[r][3] = a.w;
        rq[r][4] = b.x; rq[r][5] = b.y; rq[r][6] = b.z; rq[r][7] = b.w;
    }

    // stage the j tile (coalesced uint4 copy) + integer norms
    {
        const uint4* src = reinterpret_cast<const uint4*>(g_qx + (size_t)jb * 8);
        uint4* dst = reinterpret_cast<uint4*>(tile);
        #pragma unroll
        for (int q = 0; q < (JSEG * 8 / 4) / THR; q++)   // 4 per thread
            dst[t + q * THR] = src[t + q * THR];
        sqt[t]       = g_isq[jb + t];
        sqt[t + THR] = g_isq[jb + THR + t];
    }
    __syncthreads();

    int m[RPT][6];
    #pragma unroll
    for (int r = 0; r < RPT; r++)
        #pragma unroll
        for (int q = 0; q < 6; q++) m[r][q] = BIGI;

    #pragma unroll 2
    for (int j = 0; j < JSEG; j++) {
        const uint4 va = *reinterpret_cast<const uint4*>(&tile[j * 8]);       // broadcast
        const uint4 vb = *reinterpret_cast<const uint4*>(&tile[j * 8 + 4]);
        const int sqj = sqt[j];
        #pragma unroll
        for (int r = 0; r < RPT; r++) {
            int acc = __dp4a((int)va.x, (int)rq[r][0], 0);
            acc = __dp4a((int)va.y, (int)rq[r][1], acc);
            acc = __dp4a((int)va.z, (int)rq[r][2], acc);
            acc = __dp4a((int)va.w, (int)rq[r][3], acc);
            acc = __dp4a((int)vb.x, (int)rq[r][4], acc);
            acc = __dp4a((int)vb.y, (int)rq[r][5], acc);
            acc = __dp4a((int)vb.z, (int)rq[r][6], acc);
            acc = __dp4a((int)vb.w, (int)rq[r][7], acc);
            int d = sqj - 2 * acc;
            if (d < m[r][5]) ins6i(m[r], d);   // rare branch, co-issued
        }
    }

    #pragma unroll
    for (int r = 0; r < RPT; r++) {
        const int row = base + r * THR + t;
        const int isq = g_isq[row];
        int* dst = g_part + (size_t)row * (SPLIT * 6) + blockIdx.y * 6;
        #pragma unroll
        for (int q = 0; q < 6; q++) dst[q] = m[r][q] + isq;
    }
}

// ---------------------------------------------------------------------------
// Kernel 3: merge 24 splits -> vertex filtration value
// v = 1 - sum_{k=1..5} exp(-sqrt(max(d2_k, eps))) / 6   (m[0]=0=self dropped)
// ---------------------------------------------------------------------------
__global__ void finalize_vertex_kernel(float* __restrict__ out) {
    int i = blockIdx.x * blockDim.x + threadIdx.x;
    if (i < N_V) {
        const int* src = g_part + (size_t)i * (SPLIT * 6);
        int m[6] = {BIGI, BIGI, BIGI, BIGI, BIGI, BIGI};
        #pragma unroll 4
        for (int k = 0; k < SPLIT * 6; k++) {
            int d = src[k];
            if (d < m[5]) ins6i(m, d);
        }
        float sum = 0.f;
        #pragma unroll
        for (int q = 1; q < 6; q++) {
            float d2 = (float)m[q] * INV_S2;
            sum += expf(-sqrtf(fmaxf(d2, EPSF)));
        }
        float v = 1.f - sum * (1.f / 6.f);
        g_v[i] = v;
        out[2 * i]     = v;
        out[2 * i + 1] = 0.f;
    }
}

// ---------------------------------------------------------------------------
// Kernel 4: edge filtration, 8 edges/warp, 4 independent gathers per lane
// (measured 10.3us in R14). Reference's per-edge pair sort is a no-op
// (both outputs symmetric in (u,w)).
// ---------------------------------------------------------------------------
__global__ void __launch_bounds__(256) edge_kernel(const float* __restrict__ x,
                                                   const int* __restrict__ ei,
                                                   float* __restrict__ out) {
    const int warp = (blockIdx.x * blockDim.x + threadIdx.x) >> 5;
    const int lane = threadIdx.x & 31;
    const int k    = lane >> 2;          // edge group 0..7
    const int sub  = lane & 3;           // 8-float chunk 0..3
    const int e    = warp * 8 + k;
    if (e < N_E) {
        const int u = ei[e];
        const int w = ei[N_E + e];
        const float4* xu = reinterpret_cast<const float4*>(x + (size_t)u * D_F + sub * 8);
        const float4* xw = reinterpret_cast<const float4*>(x + (size_t)w * D_F + sub * 8);
        float4 a0 = xu[0], a1 = xu[1];   // 4 independent LDG.128 per lane
        float4 b0 = xw[0], b1 = xw[1];
        float dx = a0.x - b0.x, dy = a0.y - b0.y;
        float dz = a0.z - b0.z, dw = a0.w - b0.w;
        float s = dx * dx + dy * dy + dz * dz + dw * dw;
        dx = a1.x - b1.x; dy = a1.y - b1.y;
        dz = a1.z - b1.z; dw = a1.w - b1.w;
        s += dx * dx + dy * dy + dz * dz + dw * dw;
        s += __shfl_xor_sync(0xFFFFFFFFu, s, 1);
        s += __shfl_xor_sync(0xFFFFFFFFu, s, 2);
        if (sub == 0) {
            float n  = sqrtf(fmaxf(s, EPSF));
            float ev = fmaxf(g_v[u], g_v[w]);
            *reinterpret_cast<float2*>(out + 2 * (N_V + e)) =
                make_float2(ev, 1.f - expf(-n));
        }
    }
}

// ---------------------------------------------------------------------------
extern "C" void kernel_launch(void* const* d_in, const int* in_sizes, int n_in,
                              void* d_out, int out_size) {
    (void)in_sizes; (void)n_in; (void)out_size;
    const float* x   = (const float*)d_in[0];
    const int*   ei  = (const int*)d_in[1];
    float*       out = (float*)d_out;

    conv_kernel<<<(N_V + 255) / 256, 256>>>(x);

    dim3 grid(NBR, SPLIT);
    knn_kernel<<<grid, THR>>>();

    finalize_vertex_kernel<<<(N_V + 255) / 256, 256>>>(out);
    edge_kernel<<<(N_E / 8 + 7) / 8, 256>>>(x, ei, out);
}

// round 17
// speedup vs baseline: 1.7193x; 1.0604x over previous
#include <cuda_runtime.h>
#include <cstdint>

#define N_V    12288
#define D_F    32
#define N_E    196608
#define THR    256
#define RPT    4                  // rows per thread
#define RB     (THR * RPT)        // 1024 rows per block
#define NBR    (N_V / RB)         // 12
#define SPLIT  24
#define JSEG   (N_V / SPLIT)      // 512
#define SCALE  20.0f
#define INV_S2 (1.0f / (SCALE * SCALE))
#define EPSF   1e-12f
#define BIGI   0x7FFFFFFF

__device__ uint32_t g_qx[N_V * 8];    // int8-packed rows (tight, for knn)
__device__ int      g_isq[N_V];       // integer squared norms
__device__ uint4    g_ed[N_V * 4];    // 64B records: {q0..3},{q4..7},{isq,v,0,0},{pad}
__device__ float    g_v[N_V];
__device__ int      g_part[N_V * SPLIT * 6];

__device__ __forceinline__ void ins6i(int (&m)[6], int d) {
    int c4 = max(m[4], d);
    int c3 = max(m[3], d);
    int c2 = max(m[2], d);
    int c1 = max(m[1], d);
    int c0 = max(m[0], d);
    m[5] = min(m[5], c4);
    m[4] = min(m[4], c3);
    m[3] = min(m[3], c2);
    m[2] = min(m[2], c1);
    m[0] = min(m[0], d);
    m[1] = min(m[1], c0);
}

// ---------------------------------------------------------------------------
// Kernel 1: quantize x -> int8 (scale 20), integer squared norms; also fill
// the 64B per-vertex edge record (qrow + isq; v patched in by finalize).
// ---------------------------------------------------------------------------
__global__ void conv_kernel(const float* __restrict__ x) {
    int i = blockIdx.x * blockDim.x + threadIdx.x;
    if (i < N_V) {
        const float4* xr = reinterpret_cast<const float4*>(x + (size_t)i * D_F);
        uint32_t pk[8];
        int isq = 0;
        #pragma unroll
        for (int q = 0; q < 8; q++) {
            float4 v = xr[q];
            int q0 = __float2int_rn(fminf(fmaxf(v.x * SCALE, -127.f), 127.f));
            int q1 = __float2int_rn(fminf(fmaxf(v.y * SCALE, -127.f), 127.f));
            int q2 = __float2int_rn(fminf(fmaxf(v.z * SCALE, -127.f), 127.f));
            int q3 = __float2int_rn(fminf(fmaxf(v.w * SCALE, -127.f), 127.f));
            pk[q] = (uint32_t)(q0 & 0xFF) | ((uint32_t)(q1 & 0xFF) << 8) |
                    ((uint32_t)(q2 & 0xFF) << 16) | ((uint32_t)(q3 & 0xFF) << 24);
            isq = __dp4a((int)pk[q], (int)pk[q], isq);
        }
        g_isq[i] = isq;
        uint4* dst = reinterpret_cast<uint4*>(g_qx + (size_t)i * 8);
        dst[0] = make_uint4(pk[0], pk[1], pk[2], pk[3]);
        dst[1] = make_uint4(pk[4], pk[5], pk[6], pk[7]);
        g_ed[i * 4 + 0] = make_uint4(pk[0], pk[1], pk[2], pk[3]);
        g_ed[i * 4 + 1] = make_uint4(pk[4], pk[5], pk[6], pk[7]);
        g_ed[i * 4 + 2] = make_uint4((uint32_t)isq, 0u, 0u, 0u);
        g_ed[i * 4 + 3] = make_uint4(0u, 0u, 0u, 0u);
    }
}

// ---------------------------------------------------------------------------
// Kernel 2: int8 full-scan knn (measured at the dp4a pipe floor).
// d~2(i,j) tracked in (isq_j - 2*idot) space; isq_i folded at the end.
// 256 threads x 4 rows/thread -> 32 dp4a per j-iteration; selection rides
// the idle issue slots. Whole 512-j split staged in smem once.
// Grid (12, 24) = 288 CTAs = one balanced wave at occupancy 2.
// ---------------------------------------------------------------------------
__global__ void __launch_bounds__(THR, 2) knn_kernel() {
    __shared__ uint32_t tile[JSEG * 8];   // 16 KB
    __shared__ int      sqt[JSEG];        // 2 KB

    const int t    = threadIdx.x;
    const int base = blockIdx.x * RB;
    const int jb   = blockIdx.y * JSEG;

    uint32_t rq[RPT][8];
    #pragma unroll
    for (int r = 0; r < RPT; r++) {
        const uint4* p =
            reinterpret_cast<const uint4*>(g_qx + (size_t)(base + r * THR + t) * 8);
        uint4 a = p[0], b = p[1];
        rq[r][0] = a.x; rq[r][1] = a.y; rq[r][2] = a.z; rq[r][3] = a.w;
        rq[r][4] = b.x; rq[r][5] = b.y; rq[r][6] = b.z; rq[r][7] = b.w;
    }

    {
        const uint4* src = reinterpret_cast<const uint4*>(g_qx + (size_t)jb * 8);
        uint4* dst = reinterpret_cast<uint4*>(tile);
        #pragma unroll
        for (int q = 0; q < (JSEG * 8 / 4) / THR; q++)   // 4 per thread
            dst[t + q * THR] = src[t + q * THR];
        sqt[t]       = g_isq[jb + t];
        sqt[t + THR] = g_isq[jb + THR + t];
    }
    __syncthreads();

    int m[RPT][6];
    #pragma unroll
    for (int r = 0; r < RPT; r++)
        #pragma unroll
        for (int q = 0; q < 6; q++) m[r][q] = BIGI;

    #pragma unroll 2
    for (int j = 0; j < JSEG; j++) {
        const uint4 va = *reinterpret_cast<const uint4*>(&tile[j * 8]);       // broadcast
        const uint4 vb = *reinterpret_cast<const uint4*>(&tile[j * 8 + 4]);
        const int sqj = sqt[j];
        #pragma unroll
        for (int r = 0; r < RPT; r++) {
            int acc = __dp4a((int)va.x, (int)rq[r][0], 0);
            acc = __dp4a((int)va.y, (int)rq[r][1], acc);
            acc = __dp4a((int)va.z, (int)rq[r][2], acc);
            acc = __dp4a((int)va.w, (int)rq[r][3], acc);
            acc = __dp4a((int)vb.x, (int)rq[r][4], acc);
            acc = __dp4a((int)vb.y, (int)rq[r][5], acc);
            acc = __dp4a((int)vb.z, (int)rq[r][6], acc);
            acc = __dp4a((int)vb.w, (int)rq[r][7], acc);
            int d = sqj - 2 * acc;
            if (d < m[r][5]) ins6i(m[r], d);   // rare branch, co-issued
        }
    }

    #pragma unroll
    for (int r = 0; r < RPT; r++) {
        const int row = base + r * THR + t;
        const int isq = g_isq[row];
        int* dst = g_part + (size_t)row * (SPLIT * 6) + blockIdx.y * 6;
        #pragma unroll
        for (int q = 0; q < 6; q++) dst[q] = m[r][q] + isq;
    }
}

// ---------------------------------------------------------------------------
// Kernel 3: merge 24 splits -> vertex filtration value; patch v into the
// 64B edge record. v = 1 - sum_{k=1..5} exp(-sqrt(max(d2,eps)))/6.
// ---------------------------------------------------------------------------
__global__ void finalize_vertex_kernel(float* __restrict__ out) {
    int i = blockIdx.x * blockDim.x + threadIdx.x;
    if (i < N_V) {
        const int* src = g_part + (size_t)i * (SPLIT * 6);
        int m[6] = {BIGI, BIGI, BIGI, BIGI, BIGI, BIGI};
        #pragma unroll 4
        for (int k = 0; k < SPLIT * 6; k++) {
            int d = src[k];
            if (d < m[5]) ins6i(m, d);
        }
        float sum = 0.f;
        #pragma unroll
        for (int q = 1; q < 6; q++) {
            float d2 = (float)m[q] * INV_S2;
            sum += expf(-sqrtf(fmaxf(d2, EPSF)));
        }
        float v = 1.f - sum * (1.f / 6.f);
        g_v[i] = v;
        reinterpret_cast<uint32_t*>(g_ed)[i * 16 + 9] = __float_as_uint(v);
        out[2 * i]     = v;
        out[2 * i + 1] = 0.f;
    }
}

// ---------------------------------------------------------------------------
// Kernel 4: edge filtration from 64B packed records. 4-lane group per edge:
// ONE LDG.128 per lane per endpoint (2 wavefront-lines/edge total, vs ~5
// for the fp32 gather version). dot via predicated dp4a on lanes 0-1,
// exact integer d^2 = isq_u + isq_w - 2*dot; isq & v ride in lane 2's
// quarter of the record. Group outputs are contiguous (coalesced float2).
// Reference's per-edge pair sort is a no-op (outputs symmetric in (u,w)).
// ---------------------------------------------------------------------------
__global__ void __launch_bounds__(256) edge_kernel(const int* __restrict__ ei,
                                                   float* __restrict__ out) {
    const int warp = (blockIdx.x * blockDim.x + threadIdx.x) >> 5;
    const int lane = threadIdx.x & 31;
    const int k    = lane >> 2;          // edge group 0..7
    const int sub  = lane & 3;           // record quarter 0..3
    const int e    = warp * 8 + k;
    if (e < N_E) {
        const int u = ei[e];
        const int w = ei[N_E + e];
        const uint4 A = g_ed[u * 4 + sub];
        const uint4 B = g_ed[w * 4 + sub];
        int part = 0;
        if (sub < 2) {
            part = __dp4a((int)A.x, (int)B.x, 0);
            part = __dp4a((int)A.y, (int)B.y, part);
            part = __dp4a((int)A.z, (int)B.z, part);
            part = __dp4a((int)A.w, (int)B.w, part);
        }
        part += __shfl_xor_sync(0xFFFFFFFFu, part, 1);
        part += __shfl_xor_sync(0xFFFFFFFFu, part, 2);
        if (sub == 2) {
            const int d2i = (int)A.x + (int)B.x - 2 * part;   // exact, >= 0
            float d2 = (float)d2i * INV_S2;
            float n  = sqrtf(fmaxf(d2, EPSF));
            float ev = fmaxf(__uint_as_float(A.y), __uint_as_float(B.y));
            *reinterpret_cast<float2*>(out + 2 * (N_V + e)) =
                make_float2(ev, 1.f - expf(-n));
        }
    }
}

// ---------------------------------------------------------------------------
extern "C" void kernel_launch(void* const* d_in, const int* in_sizes, int n_in,
                              void* d_out, int out_size) {
    (void)in_sizes; (void)n_in; (void)out_size;
    const float* x   = (const float*)d_in[0];
    const int*   ei  = (const int*)d_in[1];
    float*       out = (float*)d_out;

    conv_kernel<<<(N_V + 255) / 256, 256>>>(x);

    dim3 grid(NBR, SPLIT);
    knn_kernel<<<grid, THR>>>();

    finalize_vertex_kernel<<<(N_V + 255) / 256, 256>>>(out);
    edge_kernel<<<(N_E / 8 + 7) / 8, 256>>>(ei, out);
}